// round 13
// baseline (speedup 1.0000x reference)
#include <cuda_runtime.h>
#include <cuda_fp16.h>
#include <cstdint>

#define D_DIM    256
#define ROWS     32768
#define TILE_M   64
#define THREADS  256
#define N_TILES  1024            // 512 slot (first) + 512 intent

// fp16 label tables (converted by prepass): intent [512*256], slot [1024*256]
__device__ __half Wh[(512 + 1024) * 256];
__device__ unsigned g_tile_ctr;

// smem byte offsets
#define XS   0                   // X tile: 64 rows * 512B (fp16, swizzled, pre-scaled by log2e)
#define WS   32768               // 4 x 16384 W chunk quad buffer
#define PS   98304               // P pair: 64 rows * 144B (128B data + 16B pad)
#define DEN  107520              // 128 floats (den halves)
#define TSH  108288              // tile broadcast slot
#define SMEM_BYTES 108304

static __device__ __forceinline__ uint32_t smem_u32(const void* p) {
    uint32_t a;
    asm("{ .reg .u64 t; cvta.to.shared.u64 t, %1; cvt.u32.u64 %0, t; }" : "=r"(a) : "l"(p));
    return a;
}
static __device__ __forceinline__ uint32_t pack2(float lo, float hi) {
    __half2 h = __floats2half2_rn(lo, hi);
    return reinterpret_cast<uint32_t&>(h);
}
static __device__ __forceinline__ uint32_t hex2(uint32_t x) {   // ex2 on fp16x2
    uint32_t r; asm("ex2.approx.f16x2 %0, %1;" : "=r"(r) : "r"(x)); return r;
}
static __device__ __forceinline__ float rcpf(float x) {
    float r; asm("rcp.approx.f32 %0, %1;" : "=f"(r) : "f"(x)); return r;
}

#define LDSM_X4(r0, r1, r2, r3, p) \
    asm volatile("ldmatrix.sync.aligned.m8n8.x4.shared.b16 {%0,%1,%2,%3}, [%4];" \
        : "=r"(r0), "=r"(r1), "=r"(r2), "=r"(r3) : "r"(p))
#define LDSM_X4T(r0, r1, r2, r3, p) \
    asm volatile("ldmatrix.sync.aligned.m8n8.x4.trans.shared.b16 {%0,%1,%2,%3}, [%4];" \
        : "=r"(r0), "=r"(r1), "=r"(r2), "=r"(r3) : "r"(p))
#define MMA(C, a0, a1, a2, a3, b0, b1) \
    asm volatile("mma.sync.aligned.m16n8k16.row.col.f32.f16.f16.f32 " \
        "{%0,%1,%2,%3}, {%4,%5,%6,%7}, {%8,%9}, {%0,%1,%2,%3};" \
        : "+f"((C)[0]), "+f"((C)[1]), "+f"((C)[2]), "+f"((C)[3]) \
        : "r"(a0), "r"(a1), "r"(a2), "r"(a3), "r"(b0), "r"(b1))
#define CP16(dst, src) \
    asm volatile("cp.async.cg.shared.global [%0], [%1], 16;" :: "r"(dst), "l"(src))
#define CP_COMMIT() asm volatile("cp.async.commit_group;" ::: "memory")
#define CP_WAIT0() asm volatile("cp.async.wait_group 0;" ::: "memory")

// ---- prepass: convert fp32 W tables to fp16 global; block 0 resets tile queue
__global__ void wcvt_kernel(const float* __restrict__ wi, const float* __restrict__ ws) {
    if (blockIdx.x == 0 && threadIdx.x == 0) g_tile_ctr = 0;
    int i = blockIdx.x * blockDim.x + threadIdx.x;
    __half2* dst = (__half2*)Wh;
    if (i < 32768) {
        float4 v = __ldg((const float4*)wi + i);
        dst[i * 2]     = __floats2half2_rn(v.x, v.y);
        dst[i * 2 + 1] = __floats2half2_rn(v.z, v.w);
    }
    if (i < 65536) {
        float4 v = __ldg((const float4*)ws + i);
        __half2* d2 = (__half2*)(Wh + 512 * 256);
        d2[i * 2]     = __floats2half2_rn(v.x, v.y);
        d2[i * 2 + 1] = __floats2half2_rn(v.z, v.w);
    }
}

__global__ void __launch_bounds__(THREADS, 2)
label_attn_fp16(const float* __restrict__ x_intent,
                const float* __restrict__ x_slot,
                float* __restrict__ out)
{
    extern __shared__ char smem[];
    const uint32_t sb = smem_u32(smem);
    const int tid = threadIdx.x, lane = tid & 31, warp = tid >> 5;
    const int wm = warp >> 1, wh = warp & 1;   // GEMM1 roles
    const int nw = warp;                       // GEMM2 role: n32 column slice
    const uint32_t kONES = 0x3C003C00u;        // fp16x2 {1.0, 1.0}

    // ---- per-thread addressing (tile-invariant)
    const int lo7 = lane & 7, hi = lane >> 4, g8 = ((lane >> 3) & 1) << 3;
    const int gg = lane >> 2, tt = lane & 3;
    const uint32_t xa_row = sb + XS + (wm * 16 + lo7 + g8) * 512;
    const int xa_sw = (wm * 16 + lo7 + g8) & 7;
    const uint32_t wb_row = (wh * 16 + lo7 + g8) * 512;      // GEMM1 B rows = labels
    const uint32_t pa_base = sb + PS + (lo7 + g8) * 144;     // GEMM2 A rows
    const uint32_t b2_row = (lo7 + g8) * 512;                // GEMM2 B rows = labels (k)
    const uint32_t ps_st = sb + PS + (wm * 16 + gg) * 144 + (wh * 16 + 2 * tt) * 2;
    float* dsm = (float*)(smem + DEN);
    volatile unsigned* tsh = (volatile unsigned*)(smem + TSH);

    for (;;) {
        if (tid == 0) *tsh = atomicAdd(&g_tile_ctr, 1u);
        __syncthreads();                       // broadcast; also fences prev epilogue
        unsigned t = *tsh;
        if (t >= N_TILES) break;

        const int branch = (t < 512) ? 1 : 0;  // slot tiles first (longest jobs)
        const int tile = branch ? (int)t : (int)t - 512;
        const float* __restrict__ Xin = branch ? x_slot : x_intent;
        const __half* __restrict__ Wg = Wh + (branch ? 512 * 256 : 0);
        float* __restrict__ Oout = out + (size_t)branch * ROWS * D_DIM;
        const int nch = branch ? 32 : 16;
        const long row0 = (long)tile * TILE_M;

        // ---- W chunk cp.async loader (buffer b in {0,1,2,3}); one commit per call
        auto issue_w = [&](int chunk, int b) {
            const __half* src0 = Wg + (size_t)chunk * 32 * 256;
            for (int i = tid; i < 1024; i += THREADS) {
                int r = i >> 5, c = i & 31;
                uint32_t dst = sb + WS + b * 16384 + r * 512 + ((c ^ (r & 7)) << 4);
                CP16(dst, src0 + r * 256 + c * 8);
            }
            CP_COMMIT();
        };
        issue_w(0, 0);
        issue_w(1, 1);

        // ---- X tile: fp32 gmem -> fp16 swizzled smem, pre-scaled by log2(e)
        {
            const float L2E = 1.4426950408889634f;
            const float4* X4 = (const float4*)(Xin + row0 * D_DIM);
            for (int i = tid; i < TILE_M * 64; i += THREADS) {
                int r = i >> 6, c4 = i & 63;
                float4 v = __ldg(&X4[r * 64 + c4]);
                uint32_t h0 = pack2(v.x * L2E, v.y * L2E), h1 = pack2(v.z * L2E, v.w * L2E);
                int ck = c4 >> 1;
                uint32_t dst = sb + XS + r * 512 + ((ck ^ (r & 7)) << 4) + ((c4 & 1) << 3);
                asm volatile("st.shared.v2.b32 [%0], {%1, %2};"
                             :: "r"(dst), "r"(h0), "r"(h1) : "memory");
            }
        }

        float Oa[64];
#pragma unroll
        for (int j = 0; j < 64; j++) Oa[j] = 0.0f;
        float Dacc[4];
#pragma unroll
        for (int j = 0; j < 4; j++) Dacc[j] = 0.0f;

        const int npair = nch >> 1;
        for (int j = 0; j < npair; j++) {
            const int c = 2 * j;
            const uint32_t WLo = sb + WS + ((c & 3) << 14);
            const uint32_t WHi = sb + WS + (((c + 1) & 3) << 14);
            CP_WAIT0();        // W(c), W(c+1) resident
            __syncthreads();   // sync(a): W visible; all threads past G2(j-1) -> bufs c+2,c+3 free

            if (c + 3 < nch) { issue_w(c + 2, (c + 2) & 3); issue_w(c + 3, (c + 3) & 3); }

            // ---- GEMM1 pair: each X A-frag feeds both chunks' MMAs
            float S[16];
#pragma unroll
            for (int k = 0; k < 16; k++) S[k] = 0.0f;
#pragma unroll
            for (int kk = 0; kk < 16; kk++) {
                uint32_t a0, a1, a2, a3, b0, b1, b2, b3;
                LDSM_X4(a0, a1, a2, a3, xa_row + (((2 * kk + hi) ^ xa_sw) << 4));
                LDSM_X4(b0, b1, b2, b3, WLo + wb_row + (((2 * kk + hi) ^ lo7) << 4));
                MMA(S,      a0, a1, a2, a3, b0, b2);
                MMA(S + 4,  a0, a1, a2, a3, b1, b3);
                LDSM_X4(b0, b1, b2, b3, WHi + wb_row + (((2 * kk + hi) ^ lo7) << 4));
                MMA(S + 8,  a0, a1, a2, a3, b0, b2);
                MMA(S + 12, a0, a1, a2, a3, b1, b3);
            }

            // ---- softmax piece: pack logits (fp16x2), ex2 in fp16x2, den via MMA @ ones
            uint32_t pkc[4], pkd[4];
            pkc[0] = hex2(pack2(S[0],  S[1]));  pkc[1] = hex2(pack2(S[2],  S[3]));
            pkc[2] = hex2(pack2(S[4],  S[5]));  pkc[3] = hex2(pack2(S[6],  S[7]));
            pkd[0] = hex2(pack2(S[8],  S[9]));  pkd[1] = hex2(pack2(S[10], S[11]));
            pkd[2] = hex2(pack2(S[12], S[13])); pkd[3] = hex2(pack2(S[14], S[15]));
            MMA(Dacc, pkc[0], pkc[1], pkc[2], pkc[3], kONES, kONES);   // row sums -> den
            MMA(Dacc, pkd[0], pkd[1], pkd[2], pkd[3], kONES, kONES);
            asm volatile("st.shared.b32 [%0], %1;" :: "r"(ps_st),        "r"(pkc[0]) : "memory");
            asm volatile("st.shared.b32 [%0], %1;" :: "r"(ps_st + 16),   "r"(pkc[2]) : "memory");
            asm volatile("st.shared.b32 [%0], %1;" :: "r"(ps_st + 1152), "r"(pkc[1]) : "memory");
            asm volatile("st.shared.b32 [%0], %1;" :: "r"(ps_st + 1168), "r"(pkc[3]) : "memory");
            asm volatile("st.shared.b32 [%0], %1;" :: "r"(ps_st + 64),   "r"(pkd[0]) : "memory");
            asm volatile("st.shared.b32 [%0], %1;" :: "r"(ps_st + 80),   "r"(pkd[2]) : "memory");
            asm volatile("st.shared.b32 [%0], %1;" :: "r"(ps_st + 1216), "r"(pkd[1]) : "memory");
            asm volatile("st.shared.b32 [%0], %1;" :: "r"(ps_st + 1232), "r"(pkd[3]) : "memory");
            __syncthreads();   // sync(b): P pair visible

            // ---- GEMM2 pair: warp owns cols [nw*32,+32), all 64 rows, k=64
#pragma unroll
            for (int ks = 0; ks < 4; ks++) {
                const uint32_t Wb = (ks < 2) ? WLo : WHi;
                const int ksl = ks & 1;
                uint32_t a[4][4];
#pragma unroll
                for (int mt = 0; mt < 4; mt++)
                    LDSM_X4(a[mt][0], a[mt][1], a[mt][2], a[mt][3],
                            pa_base + mt * 2304 + ks * 32 + hi * 16);
#pragma unroll
                for (int nt = 0; nt < 2; nt++) {
                    uint32_t r0, r1, r2, r3;
                    int nc_ = nw * 4 + 2 * nt + hi;
                    LDSM_X4T(r0, r1, r2, r3,
                             Wb + (ksl << 13) + b2_row + ((nc_ ^ lo7) << 4));
#pragma unroll
                    for (int mt = 0; mt < 4; mt++) {
                        MMA(Oa + (mt * 4 + nt * 2) * 4,     a[mt][0], a[mt][1], a[mt][2], a[mt][3], r0, r1);
                        MMA(Oa + (mt * 4 + nt * 2 + 1) * 4, a[mt][0], a[mt][1], a[mt][2], a[mt][3], r2, r3);
                    }
                }
            }
        }

        // ---- denominators: every column of Dacc equals the row sum; publish halves
        __syncthreads();       // all G2 done; DEN area free
        if (tt == 0) {
            dsm[wh * 64 + wm * 16 + gg]     = Dacc[0];   // row gg of warp's m-group
            dsm[wh * 64 + wm * 16 + gg + 8] = Dacc[2];   // row gg+8
        }
        __syncthreads();

        // ---- scaled store: warp nw covers rows 0..63, cols nw*32..+31
#pragma unroll
        for (int mt = 0; mt < 4; mt++) {
            const int ra_l = mt * 16 + gg;
            const float ia = rcpf(dsm[ra_l]     + dsm[64 + ra_l]);
            const float ib = rcpf(dsm[ra_l + 8] + dsm[64 + ra_l + 8]);
            const long r_a = row0 + ra_l, r_b = r_a + 8;
#pragma unroll
            for (int t4 = 0; t4 < 4; t4++) {
                int cc = nw * 32 + t4 * 8 + 2 * tt;
                int idx = (mt * 4 + t4) * 4;
                *(float2*)&Oout[r_a * 256 + cc] = make_float2(Oa[idx]     * ia, Oa[idx + 1] * ia);
                *(float2*)&Oout[r_b * 256 + cc] = make_float2(Oa[idx + 2] * ib, Oa[idx + 3] * ib);
            }
        }
    }
}

extern "C" void kernel_launch(void* const* d_in, const int* in_sizes, int n_in,
                              void* d_out, int out_size)
{
    const float* x_intent = (const float*)d_in[0];
    const float* x_slot   = (const float*)d_in[1];
    // d_in[2] = mask (unused)
    const float* w_intent = (const float*)d_in[3];
    const float* w_slot   = (const float*)d_in[4];
    float* out = (float*)d_out;

    wcvt_kernel<<<256, 256>>>(w_intent, w_slot);   // also resets g_tile_ctr

    cudaFuncSetAttribute(label_attn_fp16,
                         cudaFuncAttributeMaxDynamicSharedMemorySize, SMEM_BYTES);
    label_attn_fp16<<<296, THREADS, SMEM_BYTES>>>(x_intent, x_slot, out);
}

// round 14
// speedup vs baseline: 1.0229x; 1.0229x over previous
#include <cuda_runtime.h>
#include <cuda_fp16.h>
#include <cstdint>

#define D_DIM    256
#define ROWS     32768
#define TILE_M   64
#define THREADS  256
#define N_TILES  1024            // 512 slot (first) + 512 intent

// fp16 label tables (converted by prepass): intent [512*256], slot [1024*256]
__device__ __half Wh[(512 + 1024) * 256];
__device__ unsigned g_tile_ctr;

// smem byte offsets
#define XS   0                   // X tile: 64 rows * 512B (fp16, swizzled, pre-scaled by log2e)
#define WS   32768               // 4 x 16384 W chunk quad buffer
#define PS   98304               // P pair: 64 rows * 144B (128B data + 16B pad)
#define DEN  107520              // 128 floats (den halves)
#define TSH  108288              // tile broadcast slot
#define SMEM_BYTES 108304

static __device__ __forceinline__ uint32_t smem_u32(const void* p) {
    uint32_t a;
    asm("{ .reg .u64 t; cvta.to.shared.u64 t, %1; cvt.u32.u64 %0, t; }" : "=r"(a) : "l"(p));
    return a;
}
static __device__ __forceinline__ uint32_t pack2(float lo, float hi) {
    __half2 h = __floats2half2_rn(lo, hi);
    return reinterpret_cast<uint32_t&>(h);
}
static __device__ __forceinline__ uint32_t hex2(uint32_t x) {   // ex2 on fp16x2
    uint32_t r; asm("ex2.approx.f16x2 %0, %1;" : "=r"(r) : "r"(x)); return r;
}
static __device__ __forceinline__ float rcpf(float x) {
    float r; asm("rcp.approx.f32 %0, %1;" : "=f"(r) : "f"(x)); return r;
}
static __device__ __forceinline__ float2 unpk(uint32_t x) {
    __half2 h = reinterpret_cast<__half2&>(x);
    return __half22float2(h);
}

#define LDSM_X4(r0, r1, r2, r3, p) \
    asm volatile("ldmatrix.sync.aligned.m8n8.x4.shared.b16 {%0,%1,%2,%3}, [%4];" \
        : "=r"(r0), "=r"(r1), "=r"(r2), "=r"(r3) : "r"(p))
#define LDSM_X4T(r0, r1, r2, r3, p) \
    asm volatile("ldmatrix.sync.aligned.m8n8.x4.trans.shared.b16 {%0,%1,%2,%3}, [%4];" \
        : "=r"(r0), "=r"(r1), "=r"(r2), "=r"(r3) : "r"(p))
#define MMA(C, a0, a1, a2, a3, b0, b1) \
    asm volatile("mma.sync.aligned.m16n8k16.row.col.f32.f16.f16.f32 " \
        "{%0,%1,%2,%3}, {%4,%5,%6,%7}, {%8,%9}, {%0,%1,%2,%3};" \
        : "+f"((C)[0]), "+f"((C)[1]), "+f"((C)[2]), "+f"((C)[3]) \
        : "r"(a0), "r"(a1), "r"(a2), "r"(a3), "r"(b0), "r"(b1))
#define CP16(dst, src) \
    asm volatile("cp.async.cg.shared.global [%0], [%1], 16;" :: "r"(dst), "l"(src))
#define CP_COMMIT() asm volatile("cp.async.commit_group;" ::: "memory")
#define CP_WAIT0() asm volatile("cp.async.wait_group 0;" ::: "memory")

// ---- prepass: convert fp32 W tables to fp16 global; block 0 resets tile queue
__global__ void wcvt_kernel(const float* __restrict__ wi, const float* __restrict__ ws) {
    if (blockIdx.x == 0 && threadIdx.x == 0) g_tile_ctr = 0;
    int i = blockIdx.x * blockDim.x + threadIdx.x;
    __half2* dst = (__half2*)Wh;
    if (i < 32768) {
        float4 v = __ldg((const float4*)wi + i);
        dst[i * 2]     = __floats2half2_rn(v.x, v.y);
        dst[i * 2 + 1] = __floats2half2_rn(v.z, v.w);
    }
    if (i < 65536) {
        float4 v = __ldg((const float4*)ws + i);
        __half2* d2 = (__half2*)(Wh + 512 * 256);
        d2[i * 2]     = __floats2half2_rn(v.x, v.y);
        d2[i * 2 + 1] = __floats2half2_rn(v.z, v.w);
    }
}

__global__ void __launch_bounds__(THREADS, 2)
label_attn_fp16(const float* __restrict__ x_intent,
                const float* __restrict__ x_slot,
                float* __restrict__ out)
{
    extern __shared__ char smem[];
    const uint32_t sb = smem_u32(smem);
    const int tid = threadIdx.x, lane = tid & 31, warp = tid >> 5;
    const int wm = warp >> 1, wh = warp & 1;   // GEMM1 roles
    const int nw = warp;                       // GEMM2 role: n32 column slice

    // ---- per-thread addressing (tile-invariant)
    const int lo7 = lane & 7, hi = lane >> 4, g8 = ((lane >> 3) & 1) << 3;
    const int gg = lane >> 2, tt = lane & 3;
    const uint32_t xa_row = sb + XS + (wm * 16 + lo7 + g8) * 512;
    const int xa_sw = (wm * 16 + lo7 + g8) & 7;
    const uint32_t wb_row = (wh * 16 + lo7 + g8) * 512;      // GEMM1 B rows = labels
    const uint32_t pa_base = sb + PS + (lo7 + g8) * 144;     // GEMM2 A rows
    const uint32_t b2_row = (lo7 + g8) * 512;                // GEMM2 B rows = labels (k)
    const uint32_t ps_st = sb + PS + (wm * 16 + gg) * 144 + (wh * 16 + 2 * tt) * 2;
    float* dsm = (float*)(smem + DEN);
    volatile unsigned* tsh = (volatile unsigned*)(smem + TSH);

    for (;;) {
        if (tid == 0) *tsh = atomicAdd(&g_tile_ctr, 1u);
        __syncthreads();                       // broadcast; also fences prev epilogue
        unsigned t = *tsh;
        if (t >= N_TILES) break;

        const int branch = (t < 512) ? 1 : 0;  // slot tiles first (longest jobs)
        const int tile = branch ? (int)t : (int)t - 512;
        const float* __restrict__ Xin = branch ? x_slot : x_intent;
        const __half* __restrict__ Wg = Wh + (branch ? 512 * 256 : 0);
        float* __restrict__ Oout = out + (size_t)branch * ROWS * D_DIM;
        const int nch = branch ? 32 : 16;
        const long row0 = (long)tile * TILE_M;

        // ---- W chunk cp.async loader (buffer b in {0,1,2,3}); one commit per call
        auto issue_w = [&](int chunk, int b) {
            const __half* src0 = Wg + (size_t)chunk * 32 * 256;
            for (int i = tid; i < 1024; i += THREADS) {
                int r = i >> 5, c = i & 31;
                uint32_t dst = sb + WS + b * 16384 + r * 512 + ((c ^ (r & 7)) << 4);
                CP16(dst, src0 + r * 256 + c * 8);
            }
            CP_COMMIT();
        };
        issue_w(0, 0);
        issue_w(1, 1);

        // ---- X tile: fp32 gmem -> fp16 swizzled smem, pre-scaled by log2(e)
        //      (X feeds only GEMM1, so logits land in log2 domain -> bare ex2)
        {
            const float L2E = 1.4426950408889634f;
            const float4* X4 = (const float4*)(Xin + row0 * D_DIM);
            for (int i = tid; i < TILE_M * 64; i += THREADS) {
                int r = i >> 6, c4 = i & 63;
                float4 v = __ldg(&X4[r * 64 + c4]);
                uint32_t h0 = pack2(v.x * L2E, v.y * L2E), h1 = pack2(v.z * L2E, v.w * L2E);
                int ck = c4 >> 1;
                uint32_t dst = sb + XS + r * 512 + ((ck ^ (r & 7)) << 4) + ((c4 & 1) << 3);
                asm volatile("st.shared.v2.b32 [%0], {%1, %2};"
                             :: "r"(dst), "r"(h0), "r"(h1) : "memory");
            }
        }

        float Oa[64];
#pragma unroll
        for (int j = 0; j < 64; j++) Oa[j] = 0.0f;
        float den0 = 0.0f, den1 = 0.0f;

        const int npair = nch >> 1;
        for (int j = 0; j < npair; j++) {
            const int c = 2 * j;
            const uint32_t WLo = sb + WS + ((c & 3) << 14);
            const uint32_t WHi = sb + WS + (((c + 1) & 3) << 14);
            CP_WAIT0();        // W(c), W(c+1) resident
            __syncthreads();   // sync(a): W visible; all threads past G2(j-1) -> bufs c+2,c+3 free

            if (c + 3 < nch) { issue_w(c + 2, (c + 2) & 3); issue_w(c + 3, (c + 3) & 3); }

            // ---- GEMM1 pair: each X A-frag feeds both chunks' MMAs
            float S[16];
#pragma unroll
            for (int k = 0; k < 16; k++) S[k] = 0.0f;
#pragma unroll
            for (int kk = 0; kk < 16; kk++) {
                uint32_t a0, a1, a2, a3, b0, b1, b2, b3;
                LDSM_X4(a0, a1, a2, a3, xa_row + (((2 * kk + hi) ^ xa_sw) << 4));
                LDSM_X4(b0, b1, b2, b3, WLo + wb_row + (((2 * kk + hi) ^ lo7) << 4));
                MMA(S,      a0, a1, a2, a3, b0, b2);
                MMA(S + 4,  a0, a1, a2, a3, b1, b3);
                LDSM_X4(b0, b1, b2, b3, WHi + wb_row + (((2 * kk + hi) ^ lo7) << 4));
                MMA(S + 8,  a0, a1, a2, a3, b0, b2);
                MMA(S + 12, a0, a1, a2, a3, b1, b3);
            }

            // ---- softmax piece: pack logits (fp16x2), ex2 in fp16x2, store P pair
            uint32_t pk[8];
            pk[0] = hex2(pack2(S[0],  S[1]));  pk[1] = hex2(pack2(S[2],  S[3]));
            pk[2] = hex2(pack2(S[4],  S[5]));  pk[3] = hex2(pack2(S[6],  S[7]));
            pk[4] = hex2(pack2(S[8],  S[9]));  pk[5] = hex2(pack2(S[10], S[11]));
            pk[6] = hex2(pack2(S[12], S[13])); pk[7] = hex2(pack2(S[14], S[15]));
            asm volatile("st.shared.b32 [%0], %1;" :: "r"(ps_st),        "r"(pk[0]) : "memory");
            asm volatile("st.shared.b32 [%0], %1;" :: "r"(ps_st + 16),   "r"(pk[2]) : "memory");
            asm volatile("st.shared.b32 [%0], %1;" :: "r"(ps_st + 1152), "r"(pk[1]) : "memory");
            asm volatile("st.shared.b32 [%0], %1;" :: "r"(ps_st + 1168), "r"(pk[3]) : "memory");
            asm volatile("st.shared.b32 [%0], %1;" :: "r"(ps_st + 64),   "r"(pk[4]) : "memory");
            asm volatile("st.shared.b32 [%0], %1;" :: "r"(ps_st + 80),   "r"(pk[6]) : "memory");
            asm volatile("st.shared.b32 [%0], %1;" :: "r"(ps_st + 1216), "r"(pk[5]) : "memory");
            asm volatile("st.shared.b32 [%0], %1;" :: "r"(ps_st + 1232), "r"(pk[7]) : "memory");
            __syncthreads();   // sync(b): P pair visible

            // den adds here (fp32, from the same fp16-rounded exps stored in P);
            // overlaps G2's first operand loads
            {
                float2 f0 = unpk(pk[0]), f2 = unpk(pk[2]), f4 = unpk(pk[4]), f6 = unpk(pk[6]);
                den0 += (f0.x + f0.y) + (f2.x + f2.y) + (f4.x + f4.y) + (f6.x + f6.y);
                float2 f1 = unpk(pk[1]), f3 = unpk(pk[3]), f5 = unpk(pk[5]), f7 = unpk(pk[7]);
                den1 += (f1.x + f1.y) + (f3.x + f3.y) + (f5.x + f5.y) + (f7.x + f7.y);
            }

            // ---- GEMM2 pair: warp owns cols [nw*32,+32), all 64 rows, k=64
#pragma unroll
            for (int ks = 0; ks < 4; ks++) {
                const uint32_t Wb = (ks < 2) ? WLo : WHi;
                const int ksl = ks & 1;
                uint32_t a[4][4];
#pragma unroll
                for (int mt = 0; mt < 4; mt++)
                    LDSM_X4(a[mt][0], a[mt][1], a[mt][2], a[mt][3],
                            pa_base + mt * 2304 + ks * 32 + hi * 16);
#pragma unroll
                for (int nt = 0; nt < 2; nt++) {
                    uint32_t r0, r1, r2, r3;
                    int nc_ = nw * 4 + 2 * nt + hi;
                    LDSM_X4T(r0, r1, r2, r3,
                             Wb + (ksl << 13) + b2_row + ((nc_ ^ lo7) << 4));
#pragma unroll
                    for (int mt = 0; mt < 4; mt++) {
                        MMA(Oa + (mt * 4 + nt * 2) * 4,     a[mt][0], a[mt][1], a[mt][2], a[mt][3], r0, r1);
                        MMA(Oa + (mt * 4 + nt * 2 + 1) * 4, a[mt][0], a[mt][1], a[mt][2], a[mt][3], r2, r3);
                    }
                }
            }
        }

        // ---- denominators: quad reduce, publish halves; per-thread approx reciprocals
        den0 += __shfl_xor_sync(0xffffffff, den0, 1);
        den0 += __shfl_xor_sync(0xffffffff, den0, 2);
        den1 += __shfl_xor_sync(0xffffffff, den1, 1);
        den1 += __shfl_xor_sync(0xffffffff, den1, 2);
        __syncthreads();       // all G2 done; DEN area free
        if (tt == 0) {
            dsm[wh * 64 + wm * 16 + gg]     = den0;
            dsm[wh * 64 + wm * 16 + gg + 8] = den1;
        }
        __syncthreads();

        // ---- scaled store: warp nw covers rows 0..63, cols nw*32..+31
#pragma unroll
        for (int mt = 0; mt < 4; mt++) {
            const int ra_l = mt * 16 + gg;
            const float ia = rcpf(dsm[ra_l]     + dsm[64 + ra_l]);
            const float ib = rcpf(dsm[ra_l + 8] + dsm[64 + ra_l + 8]);
            const long r_a = row0 + ra_l, r_b = r_a + 8;
#pragma unroll
            for (int t4 = 0; t4 < 4; t4++) {
                int cc = nw * 32 + t4 * 8 + 2 * tt;
                int idx = (mt * 4 + t4) * 4;
                *(float2*)&Oout[r_a * 256 + cc] = make_float2(Oa[idx]     * ia, Oa[idx + 1] * ia);
                *(float2*)&Oout[r_b * 256 + cc] = make_float2(Oa[idx + 2] * ib, Oa[idx + 3] * ib);
            }
        }
    }
}

extern "C" void kernel_launch(void* const* d_in, const int* in_sizes, int n_in,
                              void* d_out, int out_size)
{
    const float* x_intent = (const float*)d_in[0];
    const float* x_slot   = (const float*)d_in[1];
    // d_in[2] = mask (unused)
    const float* w_intent = (const float*)d_in[3];
    const float* w_slot   = (const float*)d_in[4];
    float* out = (float*)d_out;

    wcvt_kernel<<<256, 256>>>(w_intent, w_slot);   // also resets g_tile_ctr

    cudaFuncSetAttribute(label_attn_fp16,
                         cudaFuncAttributeMaxDynamicSharedMemorySize, SMEM_BYTES);
    label_attn_fp16<<<296, THREADS, SMEM_BYTES>>>(x_intent, x_slot, out);
}

// round 15
// speedup vs baseline: 1.0233x; 1.0004x over previous
#include <cuda_runtime.h>
#include <cuda_fp16.h>
#include <cstdint>

#define D_DIM    256
#define ROWS     32768
#define TILE_M   64
#define THREADS  256
#define N_TILES  1024            // 512 slot (first) + 512 intent

// fp16 label tables (converted by prepass): intent [512*256], slot [1024*256]
__device__ __half Wh[(512 + 1024) * 256];
__device__ unsigned g_tile_ctr;

// smem byte offsets
#define XS   0                   // X tile: 64 rows * 512B (fp16, swizzled, pre-scaled by log2e)
#define WS   32768               // 4 x 16384 W chunk quad buffer
#define PS   98304               // P pair: 64 rows * 144B (128B data + 16B pad)
#define DEN  107520              // 128 floats (den halves)
#define TSH  108288              // tile broadcast slot
#define SMEM_BYTES 108304

static __device__ __forceinline__ uint32_t smem_u32(const void* p) {
    uint32_t a;
    asm("{ .reg .u64 t; cvta.to.shared.u64 t, %1; cvt.u32.u64 %0, t; }" : "=r"(a) : "l"(p));
    return a;
}
static __device__ __forceinline__ uint32_t pack2(float lo, float hi) {
    __half2 h = __floats2half2_rn(lo, hi);
    return reinterpret_cast<uint32_t&>(h);
}
static __device__ __forceinline__ uint32_t hex2(uint32_t x) {   // ex2 on fp16x2
    uint32_t r; asm("ex2.approx.f16x2 %0, %1;" : "=r"(r) : "r"(x)); return r;
}
static __device__ __forceinline__ float rcpf(float x) {
    float r; asm("rcp.approx.f32 %0, %1;" : "=f"(r) : "f"(x)); return r;
}
static __device__ __forceinline__ float2 unpk(uint32_t x) {
    __half2 h = reinterpret_cast<__half2&>(x);
    return __half22float2(h);
}

#define LDSM_X4(r0, r1, r2, r3, p) \
    asm volatile("ldmatrix.sync.aligned.m8n8.x4.shared.b16 {%0,%1,%2,%3}, [%4];" \
        : "=r"(r0), "=r"(r1), "=r"(r2), "=r"(r3) : "r"(p))
#define LDSM_X4T(r0, r1, r2, r3, p) \
    asm volatile("ldmatrix.sync.aligned.m8n8.x4.trans.shared.b16 {%0,%1,%2,%3}, [%4];" \
        : "=r"(r0), "=r"(r1), "=r"(r2), "=r"(r3) : "r"(p))
#define MMA(C, a0, a1, a2, a3, b0, b1) \
    asm volatile("mma.sync.aligned.m16n8k16.row.col.f32.f16.f16.f32 " \
        "{%0,%1,%2,%3}, {%4,%5,%6,%7}, {%8,%9}, {%0,%1,%2,%3};" \
        : "+f"((C)[0]), "+f"((C)[1]), "+f"((C)[2]), "+f"((C)[3]) \
        : "r"(a0), "r"(a1), "r"(a2), "r"(a3), "r"(b0), "r"(b1))
#define CP16(dst, src) \
    asm volatile("cp.async.cg.shared.global [%0], [%1], 16;" :: "r"(dst), "l"(src))
#define CP_COMMIT() asm volatile("cp.async.commit_group;" ::: "memory")
#define CP_WAIT0() asm volatile("cp.async.wait_group 0;" ::: "memory")

// ---- prepass: convert fp32 W tables to fp16 global; block 0 resets tile queue
__global__ void wcvt_kernel(const float* __restrict__ wi, const float* __restrict__ ws) {
    if (blockIdx.x == 0 && threadIdx.x == 0) g_tile_ctr = 0;
    int i = blockIdx.x * blockDim.x + threadIdx.x;
    __half2* dst = (__half2*)Wh;
    if (i < 32768) {
        float4 v = __ldg((const float4*)wi + i);
        dst[i * 2]     = __floats2half2_rn(v.x, v.y);
        dst[i * 2 + 1] = __floats2half2_rn(v.z, v.w);
    }
    if (i < 65536) {
        float4 v = __ldg((const float4*)ws + i);
        __half2* d2 = (__half2*)(Wh + 512 * 256);
        d2[i * 2]     = __floats2half2_rn(v.x, v.y);
        d2[i * 2 + 1] = __floats2half2_rn(v.z, v.w);
    }
}

__global__ void __launch_bounds__(THREADS, 2)
label_attn_fp16(const float* __restrict__ x_intent,
                const float* __restrict__ x_slot,
                float* __restrict__ out)
{
    extern __shared__ char smem[];
    const uint32_t sb = smem_u32(smem);
    const int tid = threadIdx.x, lane = tid & 31, warp = tid >> 5;
    const int wm = warp >> 1, wh = warp & 1;   // GEMM1 roles
    const int nw = warp;                       // GEMM2 role: n32 column slice

    // ---- per-thread addressing (tile-invariant)
    const int lo7 = lane & 7, hi = lane >> 4, g8 = ((lane >> 3) & 1) << 3;
    const int gg = lane >> 2, tt = lane & 3;
    const uint32_t xa_row = sb + XS + (wm * 16 + lo7 + g8) * 512;
    const int xa_sw = (wm * 16 + lo7 + g8) & 7;
    const uint32_t wb_row = (wh * 16 + lo7 + g8) * 512;      // GEMM1 B rows = labels
    const uint32_t pa_base = sb + PS + (lo7 + g8) * 144;     // GEMM2 A rows
    const uint32_t b2_row = (lo7 + g8) * 512;                // GEMM2 B rows = labels (k)
    const uint32_t ps_st = sb + PS + (wm * 16 + gg) * 144 + (wh * 16 + 2 * tt) * 2;
    float* dsm = (float*)(smem + DEN);
    volatile unsigned* tsh = (volatile unsigned*)(smem + TSH);

    for (;;) {
        if (tid == 0) *tsh = atomicAdd(&g_tile_ctr, 1u);
        __syncthreads();                       // broadcast; also fences prev epilogue
        unsigned t = *tsh;
        if (t >= N_TILES) break;

        const int branch = (t < 512) ? 1 : 0;  // slot tiles first (longest jobs)
        const int tile = branch ? (int)t : (int)t - 512;
        const float* __restrict__ Xin = branch ? x_slot : x_intent;
        const __half* __restrict__ Wg = Wh + (branch ? 512 * 256 : 0);
        float* __restrict__ Oout = out + (size_t)branch * ROWS * D_DIM;
        const int nch = branch ? 32 : 16;
        const long row0 = (long)tile * TILE_M;

        // ---- W chunk cp.async loader (buffer b in {0,1,2,3}); one commit per call
        auto issue_w = [&](int chunk, int b) {
            const __half* src0 = Wg + (size_t)chunk * 32 * 256;
            for (int i = tid; i < 1024; i += THREADS) {
                int r = i >> 5, c = i & 31;
                uint32_t dst = sb + WS + b * 16384 + r * 512 + ((c ^ (r & 7)) << 4);
                CP16(dst, src0 + r * 256 + c * 8);
            }
            CP_COMMIT();
        };
        issue_w(0, 0);
        issue_w(1, 1);

        // ---- X tile: fp32 gmem -> fp16 swizzled smem, pre-scaled by log2(e)
        //      (X feeds only GEMM1, so logits land in log2 domain -> bare ex2)
        {
            const float L2E = 1.4426950408889634f;
            const float4* X4 = (const float4*)(Xin + row0 * D_DIM);
            for (int i = tid; i < TILE_M * 64; i += THREADS) {
                int r = i >> 6, c4 = i & 63;
                float4 v = __ldg(&X4[r * 64 + c4]);
                uint32_t h0 = pack2(v.x * L2E, v.y * L2E), h1 = pack2(v.z * L2E, v.w * L2E);
                int ck = c4 >> 1;
                uint32_t dst = sb + XS + r * 512 + ((ck ^ (r & 7)) << 4) + ((c4 & 1) << 3);
                asm volatile("st.shared.v2.b32 [%0], {%1, %2};"
                             :: "r"(dst), "r"(h0), "r"(h1) : "memory");
            }
        }

        float Oa[64];
#pragma unroll
        for (int j = 0; j < 64; j++) Oa[j] = 0.0f;
        float den0 = 0.0f, den1 = 0.0f;

        const int npair = nch >> 1;
        for (int j = 0; j < npair; j++) {
            const int c = 2 * j;
            const uint32_t WLo = sb + WS + ((c & 3) << 14);
            const uint32_t WHi = sb + WS + (((c + 1) & 3) << 14);
            CP_WAIT0();        // W(c), W(c+1) resident
            __syncthreads();   // sync(a): W visible; all threads past G2(j-1) -> bufs c+2,c+3 free

            if (c + 3 < nch) { issue_w(c + 2, (c + 2) & 3); issue_w(c + 3, (c + 3) & 3); }

            // ---- GEMM1 pair: each X A-frag feeds both chunks' MMAs
            float S[16];
#pragma unroll
            for (int k = 0; k < 16; k++) S[k] = 0.0f;
#pragma unroll
            for (int kk = 0; kk < 16; kk++) {
                uint32_t a0, a1, a2, a3, b0, b1, b2, b3;
                LDSM_X4(a0, a1, a2, a3, xa_row + (((2 * kk + hi) ^ xa_sw) << 4));
                LDSM_X4(b0, b1, b2, b3, WLo + wb_row + (((2 * kk + hi) ^ lo7) << 4));
                MMA(S,      a0, a1, a2, a3, b0, b2);
                MMA(S + 4,  a0, a1, a2, a3, b1, b3);
                LDSM_X4(b0, b1, b2, b3, WHi + wb_row + (((2 * kk + hi) ^ lo7) << 4));
                MMA(S + 8,  a0, a1, a2, a3, b0, b2);
                MMA(S + 12, a0, a1, a2, a3, b1, b3);
            }

            // ---- softmax piece: pack logits (fp16x2), ex2 in fp16x2, store P pair
            uint32_t pk[8];
            pk[0] = hex2(pack2(S[0],  S[1]));  pk[1] = hex2(pack2(S[2],  S[3]));
            pk[2] = hex2(pack2(S[4],  S[5]));  pk[3] = hex2(pack2(S[6],  S[7]));
            pk[4] = hex2(pack2(S[8],  S[9]));  pk[5] = hex2(pack2(S[10], S[11]));
            pk[6] = hex2(pack2(S[12], S[13])); pk[7] = hex2(pack2(S[14], S[15]));
            asm volatile("st.shared.b32 [%0], %1;" :: "r"(ps_st),        "r"(pk[0]) : "memory");
            asm volatile("st.shared.b32 [%0], %1;" :: "r"(ps_st + 16),   "r"(pk[2]) : "memory");
            asm volatile("st.shared.b32 [%0], %1;" :: "r"(ps_st + 1152), "r"(pk[1]) : "memory");
            asm volatile("st.shared.b32 [%0], %1;" :: "r"(ps_st + 1168), "r"(pk[3]) : "memory");
            asm volatile("st.shared.b32 [%0], %1;" :: "r"(ps_st + 64),   "r"(pk[4]) : "memory");
            asm volatile("st.shared.b32 [%0], %1;" :: "r"(ps_st + 80),   "r"(pk[6]) : "memory");
            asm volatile("st.shared.b32 [%0], %1;" :: "r"(ps_st + 1216), "r"(pk[5]) : "memory");
            asm volatile("st.shared.b32 [%0], %1;" :: "r"(ps_st + 1232), "r"(pk[7]) : "memory");
            __syncthreads();   // sync(b): P pair visible

            // den adds here (fp32, from the same fp16-rounded exps stored in P);
            // overlaps G2's first operand loads
            {
                float2 f0 = unpk(pk[0]), f2 = unpk(pk[2]), f4 = unpk(pk[4]), f6 = unpk(pk[6]);
                den0 += (f0.x + f0.y) + (f2.x + f2.y) + (f4.x + f4.y) + (f6.x + f6.y);
                float2 f1 = unpk(pk[1]), f3 = unpk(pk[3]), f5 = unpk(pk[5]), f7 = unpk(pk[7]);
                den1 += (f1.x + f1.y) + (f3.x + f3.y) + (f5.x + f5.y) + (f7.x + f7.y);
            }

            // ---- GEMM2 pair: warp owns cols [nw*32,+32), all 64 rows, k=64
#pragma unroll
            for (int ks = 0; ks < 4; ks++) {
                const uint32_t Wb = (ks < 2) ? WLo : WHi;
                const int ksl = ks & 1;
                uint32_t a[4][4];
#pragma unroll
                for (int mt = 0; mt < 4; mt++)
                    LDSM_X4(a[mt][0], a[mt][1], a[mt][2], a[mt][3],
                            pa_base + mt * 2304 + ks * 32 + hi * 16);
#pragma unroll
                for (int nt = 0; nt < 2; nt++) {
                    uint32_t r0, r1, r2, r3;
                    int nc_ = nw * 4 + 2 * nt + hi;
                    LDSM_X4T(r0, r1, r2, r3,
                             Wb + (ksl << 13) + b2_row + ((nc_ ^ lo7) << 4));
#pragma unroll
                    for (int mt = 0; mt < 4; mt++) {
                        MMA(Oa + (mt * 4 + nt * 2) * 4,     a[mt][0], a[mt][1], a[mt][2], a[mt][3], r0, r1);
                        MMA(Oa + (mt * 4 + nt * 2 + 1) * 4, a[mt][0], a[mt][1], a[mt][2], a[mt][3], r2, r3);
                    }
                }
            }
        }

        // ---- denominators: quad reduce, publish halves; per-thread approx reciprocals
        den0 += __shfl_xor_sync(0xffffffff, den0, 1);
        den0 += __shfl_xor_sync(0xffffffff, den0, 2);
        den1 += __shfl_xor_sync(0xffffffff, den1, 1);
        den1 += __shfl_xor_sync(0xffffffff, den1, 2);
        __syncthreads();       // all G2 done; DEN area free
        if (tt == 0) {
            dsm[wh * 64 + wm * 16 + gg]     = den0;
            dsm[wh * 64 + wm * 16 + gg + 8] = den1;
        }
        __syncthreads();

        // ---- scaled store: warp nw covers rows 0..63, cols nw*32..+31
#pragma unroll
        for (int mt = 0; mt < 4; mt++) {
            const int ra_l = mt * 16 + gg;
            const float ia = rcpf(dsm[ra_l]     + dsm[64 + ra_l]);
            const float ib = rcpf(dsm[ra_l + 8] + dsm[64 + ra_l + 8]);
            const long r_a = row0 + ra_l, r_b = r_a + 8;
#pragma unroll
            for (int t4 = 0; t4 < 4; t4++) {
                int cc = nw * 32 + t4 * 8 + 2 * tt;
                int idx = (mt * 4 + t4) * 4;
                *(float2*)&Oout[r_a * 256 + cc] = make_float2(Oa[idx]     * ia, Oa[idx + 1] * ia);
                *(float2*)&Oout[r_b * 256 + cc] = make_float2(Oa[idx + 2] * ib, Oa[idx + 3] * ib);
            }
        }
    }
}

extern "C" void kernel_launch(void* const* d_in, const int* in_sizes, int n_in,
                              void* d_out, int out_size)
{
    const float* x_intent = (const float*)d_in[0];
    const float* x_slot   = (const float*)d_in[1];
    // d_in[2] = mask (unused)
    const float* w_intent = (const float*)d_in[3];
    const float* w_slot   = (const float*)d_in[4];
    float* out = (float*)d_out;

    wcvt_kernel<<<256, 256>>>(w_intent, w_slot);   // also resets g_tile_ctr

    cudaFuncSetAttribute(label_attn_fp16,
                         cudaFuncAttributeMaxDynamicSharedMemorySize, SMEM_BYTES);
    label_attn_fp16<<<296, THREADS, SMEM_BYTES>>>(x_intent, x_slot, out);
}

// round 16
// speedup vs baseline: 1.0251x; 1.0018x over previous
#include <cuda_runtime.h>
#include <cuda_fp16.h>
#include <cstdint>

#define D_DIM    256
#define ROWS     32768
#define TILE_M   64
#define THREADS  256
#define N_TILES  1024            // 512 slot (first) + 512 intent

// fp16 label tables (converted by prepass): intent [512*256], slot [1024*256]
__device__ __half Wh[(512 + 1024) * 256];
__device__ unsigned g_tile_ctr;

// smem byte offsets
#define XS   0                   // X tile: 64 rows * 512B (fp16, swizzled, pre-scaled by log2e)
#define WS   32768               // 4 x 16384 W chunk quad buffer
#define PS   98304               // P pair: 64 rows * 144B (128B data + 16B pad)
#define DEN  107520              // 128 floats (den halves)
#define TSH  108288              // tile broadcast slot
#define SMEM_BYTES 108304

static __device__ __forceinline__ uint32_t smem_u32(const void* p) {
    uint32_t a;
    asm("{ .reg .u64 t; cvta.to.shared.u64 t, %1; cvt.u32.u64 %0, t; }" : "=r"(a) : "l"(p));
    return a;
}
static __device__ __forceinline__ uint32_t pack2(float lo, float hi) {
    __half2 h = __floats2half2_rn(lo, hi);
    return reinterpret_cast<uint32_t&>(h);
}
static __device__ __forceinline__ uint32_t hex2(uint32_t x) {   // ex2 on fp16x2
    uint32_t r; asm("ex2.approx.f16x2 %0, %1;" : "=r"(r) : "r"(x)); return r;
}
static __device__ __forceinline__ float rcpf(float x) {
    float r; asm("rcp.approx.f32 %0, %1;" : "=f"(r) : "f"(x)); return r;
}
static __device__ __forceinline__ float2 unpk(uint32_t x) {
    __half2 h = reinterpret_cast<__half2&>(x);
    return __half22float2(h);
}

#define LDSM_X4(r0, r1, r2, r3, p) \
    asm volatile("ldmatrix.sync.aligned.m8n8.x4.shared.b16 {%0,%1,%2,%3}, [%4];" \
        : "=r"(r0), "=r"(r1), "=r"(r2), "=r"(r3) : "r"(p))
#define LDSM_X4T(r0, r1, r2, r3, p) \
    asm volatile("ldmatrix.sync.aligned.m8n8.x4.trans.shared.b16 {%0,%1,%2,%3}, [%4];" \
        : "=r"(r0), "=r"(r1), "=r"(r2), "=r"(r3) : "r"(p))
#define MMA(C, a0, a1, a2, a3, b0, b1) \
    asm volatile("mma.sync.aligned.m16n8k16.row.col.f32.f16.f16.f32 " \
        "{%0,%1,%2,%3}, {%4,%5,%6,%7}, {%8,%9}, {%0,%1,%2,%3};" \
        : "+f"((C)[0]), "+f"((C)[1]), "+f"((C)[2]), "+f"((C)[3]) \
        : "r"(a0), "r"(a1), "r"(a2), "r"(a3), "r"(b0), "r"(b1))
#define CP16(dst, src) \
    asm volatile("cp.async.cg.shared.global [%0], [%1], 16;" :: "r"(dst), "l"(src))
#define CP_COMMIT() asm volatile("cp.async.commit_group;" ::: "memory")
#define CP_WAIT0() asm volatile("cp.async.wait_group 0;" ::: "memory")

// ---- prepass: convert fp32 W tables to fp16 global; block 0 resets tile queue
__global__ void wcvt_kernel(const float* __restrict__ wi, const float* __restrict__ ws) {
    if (blockIdx.x == 0 && threadIdx.x == 0) g_tile_ctr = 0;
    int i = blockIdx.x * blockDim.x + threadIdx.x;
    __half2* dst = (__half2*)Wh;
    if (i < 32768) {
        float4 v = __ldg((const float4*)wi + i);
        dst[i * 2]     = __floats2half2_rn(v.x, v.y);
        dst[i * 2 + 1] = __floats2half2_rn(v.z, v.w);
    }
    if (i < 65536) {
        float4 v = __ldg((const float4*)ws + i);
        __half2* d2 = (__half2*)(Wh + 512 * 256);
        d2[i * 2]     = __floats2half2_rn(v.x, v.y);
        d2[i * 2 + 1] = __floats2half2_rn(v.z, v.w);
    }
}

__global__ void __launch_bounds__(THREADS, 2)
label_attn_fp16(const float* __restrict__ x_intent,
                const float* __restrict__ x_slot,
                float* __restrict__ out)
{
    extern __shared__ char smem[];
    const uint32_t sb = smem_u32(smem);
    const int tid = threadIdx.x, lane = tid & 31, warp = tid >> 5;
    const int wm = warp >> 1, wh = warp & 1;   // GEMM1 roles
    const int nw = warp;                       // GEMM2 role: n32 column slice

    // ---- per-thread addressing (tile-invariant)
    const int lo7 = lane & 7, hi = lane >> 4, g8 = ((lane >> 3) & 1) << 3;
    const int gg = lane >> 2, tt = lane & 3;
    const uint32_t xa_row = sb + XS + (wm * 16 + lo7 + g8) * 512;
    const int xa_sw = (wm * 16 + lo7 + g8) & 7;
    const uint32_t wb_row = (wh * 16 + lo7 + g8) * 512;      // GEMM1 B rows = labels
    const uint32_t pa_base = sb + PS + (lo7 + g8) * 144;     // GEMM2 A rows
    const uint32_t b2_row = (lo7 + g8) * 512;                // GEMM2 B rows = labels (k)
    const uint32_t ps_st = sb + PS + (wm * 16 + gg) * 144 + (wh * 16 + 2 * tt) * 2;
    float* dsm = (float*)(smem + DEN);
    volatile unsigned* tsh = (volatile unsigned*)(smem + TSH);

    for (;;) {
        if (tid == 0) *tsh = atomicAdd(&g_tile_ctr, 1u);
        __syncthreads();                       // broadcast; also fences prev epilogue
        unsigned t = *tsh;
        if (t >= N_TILES) break;

        const int branch = (t < 512) ? 1 : 0;  // slot tiles first (longest jobs)
        const int tile = branch ? (int)t : (int)t - 512;
        const float* __restrict__ Xin = branch ? x_slot : x_intent;
        const __half* __restrict__ Wg = Wh + (branch ? 512 * 256 : 0);
        float* __restrict__ Oout = out + (size_t)branch * ROWS * D_DIM;
        const int nch = branch ? 32 : 16;
        const long row0 = (long)tile * TILE_M;

        // ---- W chunk cp.async loader (buffer b in {0,1,2,3}); one commit per call
        auto issue_w = [&](int chunk, int b) {
            const __half* src0 = Wg + (size_t)chunk * 32 * 256;
            for (int i = tid; i < 1024; i += THREADS) {
                int r = i >> 5, c = i & 31;
                uint32_t dst = sb + WS + b * 16384 + r * 512 + ((c ^ (r & 7)) << 4);
                CP16(dst, src0 + r * 256 + c * 8);
            }
            CP_COMMIT();
        };
        issue_w(0, 0);
        issue_w(1, 1);

        // ---- X tile: fp32 gmem -> fp16 swizzled smem, pre-scaled by log2(e)
        //      (X feeds only GEMM1, so logits land in log2 domain -> bare ex2)
        {
            const float L2E = 1.4426950408889634f;
            const float4* X4 = (const float4*)(Xin + row0 * D_DIM);
            for (int i = tid; i < TILE_M * 64; i += THREADS) {
                int r = i >> 6, c4 = i & 63;
                float4 v = __ldg(&X4[r * 64 + c4]);
                uint32_t h0 = pack2(v.x * L2E, v.y * L2E), h1 = pack2(v.z * L2E, v.w * L2E);
                int ck = c4 >> 1;
                uint32_t dst = sb + XS + r * 512 + ((ck ^ (r & 7)) << 4) + ((c4 & 1) << 3);
                asm volatile("st.shared.v2.b32 [%0], {%1, %2};"
                             :: "r"(dst), "r"(h0), "r"(h1) : "memory");
            }
        }

        float Oa[64];
#pragma unroll
        for (int j = 0; j < 64; j++) Oa[j] = 0.0f;
        float den0 = 0.0f, den1 = 0.0f;

        const int npair = nch >> 1;
        for (int j = 0; j < npair; j++) {
            const int c = 2 * j;
            const uint32_t WLo = sb + WS + ((c & 3) << 14);
            const uint32_t WHi = sb + WS + (((c + 1) & 3) << 14);
            CP_WAIT0();        // W(c), W(c+1) resident
            __syncthreads();   // sync(a): W visible; all threads past G2(j-1) -> bufs c+2,c+3 free

            if (c + 3 < nch) { issue_w(c + 2, (c + 2) & 3); issue_w(c + 3, (c + 3) & 3); }

            // ---- GEMM1 pair: each X A-frag feeds both chunks' MMAs
            float S[16];
#pragma unroll
            for (int k = 0; k < 16; k++) S[k] = 0.0f;
#pragma unroll
            for (int kk = 0; kk < 16; kk++) {
                uint32_t a0, a1, a2, a3, b0, b1, b2, b3;
                LDSM_X4(a0, a1, a2, a3, xa_row + (((2 * kk + hi) ^ xa_sw) << 4));
                LDSM_X4(b0, b1, b2, b3, WLo + wb_row + (((2 * kk + hi) ^ lo7) << 4));
                MMA(S,      a0, a1, a2, a3, b0, b2);
                MMA(S + 4,  a0, a1, a2, a3, b1, b3);
                LDSM_X4(b0, b1, b2, b3, WHi + wb_row + (((2 * kk + hi) ^ lo7) << 4));
                MMA(S + 8,  a0, a1, a2, a3, b0, b2);
                MMA(S + 12, a0, a1, a2, a3, b1, b3);
            }

            // ---- softmax piece: pack logits (fp16x2), ex2 in fp16x2, store P pair
            uint32_t pk[8];
            pk[0] = hex2(pack2(S[0],  S[1]));  pk[1] = hex2(pack2(S[2],  S[3]));
            pk[2] = hex2(pack2(S[4],  S[5]));  pk[3] = hex2(pack2(S[6],  S[7]));
            pk[4] = hex2(pack2(S[8],  S[9]));  pk[5] = hex2(pack2(S[10], S[11]));
            pk[6] = hex2(pack2(S[12], S[13])); pk[7] = hex2(pack2(S[14], S[15]));
            asm volatile("st.shared.b32 [%0], %1;" :: "r"(ps_st),        "r"(pk[0]) : "memory");
            asm volatile("st.shared.b32 [%0], %1;" :: "r"(ps_st + 16),   "r"(pk[2]) : "memory");
            asm volatile("st.shared.b32 [%0], %1;" :: "r"(ps_st + 1152), "r"(pk[1]) : "memory");
            asm volatile("st.shared.b32 [%0], %1;" :: "r"(ps_st + 1168), "r"(pk[3]) : "memory");
            asm volatile("st.shared.b32 [%0], %1;" :: "r"(ps_st + 64),   "r"(pk[4]) : "memory");
            asm volatile("st.shared.b32 [%0], %1;" :: "r"(ps_st + 80),   "r"(pk[6]) : "memory");
            asm volatile("st.shared.b32 [%0], %1;" :: "r"(ps_st + 1216), "r"(pk[5]) : "memory");
            asm volatile("st.shared.b32 [%0], %1;" :: "r"(ps_st + 1232), "r"(pk[7]) : "memory");
            __syncthreads();   // sync(b): P pair visible

            // den adds here (fp32, from the same fp16-rounded exps stored in P);
            // overlaps G2's first operand loads
            {
                float2 f0 = unpk(pk[0]), f2 = unpk(pk[2]), f4 = unpk(pk[4]), f6 = unpk(pk[6]);
                den0 += (f0.x + f0.y) + (f2.x + f2.y) + (f4.x + f4.y) + (f6.x + f6.y);
                float2 f1 = unpk(pk[1]), f3 = unpk(pk[3]), f5 = unpk(pk[5]), f7 = unpk(pk[7]);
                den1 += (f1.x + f1.y) + (f3.x + f3.y) + (f5.x + f5.y) + (f7.x + f7.y);
            }

            // ---- GEMM2 pair: warp owns cols [nw*32,+32), all 64 rows, k=64
#pragma unroll
            for (int ks = 0; ks < 4; ks++) {
                const uint32_t Wb = (ks < 2) ? WLo : WHi;
                const int ksl = ks & 1;
                uint32_t a[4][4];
#pragma unroll
                for (int mt = 0; mt < 4; mt++)
                    LDSM_X4(a[mt][0], a[mt][1], a[mt][2], a[mt][3],
                            pa_base + mt * 2304 + ks * 32 + hi * 16);
#pragma unroll
                for (int nt = 0; nt < 2; nt++) {
                    uint32_t r0, r1, r2, r3;
                    int nc_ = nw * 4 + 2 * nt + hi;
                    LDSM_X4T(r0, r1, r2, r3,
                             Wb + (ksl << 13) + b2_row + ((nc_ ^ lo7) << 4));
#pragma unroll
                    for (int mt = 0; mt < 4; mt++) {
                        MMA(Oa + (mt * 4 + nt * 2) * 4,     a[mt][0], a[mt][1], a[mt][2], a[mt][3], r0, r1);
                        MMA(Oa + (mt * 4 + nt * 2 + 1) * 4, a[mt][0], a[mt][1], a[mt][2], a[mt][3], r2, r3);
                    }
                }
            }
        }

        // ---- denominators: quad reduce, publish halves; per-thread approx reciprocals
        den0 += __shfl_xor_sync(0xffffffff, den0, 1);
        den0 += __shfl_xor_sync(0xffffffff, den0, 2);
        den1 += __shfl_xor_sync(0xffffffff, den1, 1);
        den1 += __shfl_xor_sync(0xffffffff, den1, 2);
        __syncthreads();       // all G2 done; DEN area free
        if (tt == 0) {
            dsm[wh * 64 + wm * 16 + gg]     = den0;
            dsm[wh * 64 + wm * 16 + gg + 8] = den1;
        }
        __syncthreads();

        // ---- scaled store: warp nw covers rows 0..63, cols nw*32..+31
#pragma unroll
        for (int mt = 0; mt < 4; mt++) {
            const int ra_l = mt * 16 + gg;
            const float ia = rcpf(dsm[ra_l]     + dsm[64 + ra_l]);
            const float ib = rcpf(dsm[ra_l + 8] + dsm[64 + ra_l + 8]);
            const long r_a = row0 + ra_l, r_b = r_a + 8;
#pragma unroll
            for (int t4 = 0; t4 < 4; t4++) {
                int cc = nw * 32 + t4 * 8 + 2 * tt;
                int idx = (mt * 4 + t4) * 4;
                *(float2*)&Oout[r_a * 256 + cc] = make_float2(Oa[idx]     * ia, Oa[idx + 1] * ia);
                *(float2*)&Oout[r_b * 256 + cc] = make_float2(Oa[idx + 2] * ib, Oa[idx + 3] * ib);
            }
        }
    }
}

extern "C" void kernel_launch(void* const* d_in, const int* in_sizes, int n_in,
                              void* d_out, int out_size)
{
    const float* x_intent = (const float*)d_in[0];
    const float* x_slot   = (const float*)d_in[1];
    // d_in[2] = mask (unused)
    const float* w_intent = (const float*)d_in[3];
    const float* w_slot   = (const float*)d_in[4];
    float* out = (float*)d_out;

    wcvt_kernel<<<256, 256>>>(w_intent, w_slot);   // also resets g_tile_ctr

    cudaFuncSetAttribute(label_attn_fp16,
                         cudaFuncAttributeMaxDynamicSharedMemorySize, SMEM_BYTES);
    label_attn_fp16<<<296, THREADS, SMEM_BYTES>>>(x_intent, x_slot, out);
}

// round 17
// speedup vs baseline: 1.0440x; 1.0185x over previous
#include <cuda_runtime.h>
#include <cuda_fp16.h>
#include <cstdint>

#define D_DIM    256
#define ROWS     32768
#define TILE_M   64
#define THREADS  256
#define N_TILES  1024            // 512 slot (first) + 512 intent

// fp16 label tables (converted by prepass): intent [512*256], slot [1024*256]
__device__ __half Wh[(512 + 1024) * 256];
__device__ unsigned g_tile_ctr;

// smem byte offsets
#define XS   0                   // X tile: 64 rows * 512B (fp16, swizzled, pre-scaled by log2e)
#define WS   32768               // 4 x 16384 W chunk quad buffer
#define PS   98304               // P pair: 64 rows * 144B (128B data + 16B pad)
#define DEN  107520              // 128 floats (den halves)
#define TSH  108288              // tile broadcast slot
#define SMEM_BYTES 108304

static __device__ __forceinline__ uint32_t smem_u32(const void* p) {
    uint32_t a;
    asm("{ .reg .u64 t; cvta.to.shared.u64 t, %1; cvt.u32.u64 %0, t; }" : "=r"(a) : "l"(p));
    return a;
}
static __device__ __forceinline__ uint32_t pack2(float lo, float hi) {
    __half2 h = __floats2half2_rn(lo, hi);
    return reinterpret_cast<uint32_t&>(h);
}
static __device__ __forceinline__ uint32_t hex2(uint32_t x) {   // ex2 on fp16x2
    uint32_t r; asm("ex2.approx.f16x2 %0, %1;" : "=r"(r) : "r"(x)); return r;
}
static __device__ __forceinline__ float rcpf(float x) {
    float r; asm("rcp.approx.f32 %0, %1;" : "=f"(r) : "f"(x)); return r;
}
static __device__ __forceinline__ float2 unpk(uint32_t x) {
    __half2 h = reinterpret_cast<__half2&>(x);
    return __half22float2(h);
}
static __device__ __forceinline__ void pfl2(const void* p) {
    asm volatile("prefetch.global.L2 [%0];" :: "l"(p));
}

#define LDSM_X4(r0, r1, r2, r3, p) \
    asm volatile("ldmatrix.sync.aligned.m8n8.x4.shared.b16 {%0,%1,%2,%3}, [%4];" \
        : "=r"(r0), "=r"(r1), "=r"(r2), "=r"(r3) : "r"(p))
#define LDSM_X4T(r0, r1, r2, r3, p) \
    asm volatile("ldmatrix.sync.aligned.m8n8.x4.trans.shared.b16 {%0,%1,%2,%3}, [%4];" \
        : "=r"(r0), "=r"(r1), "=r"(r2), "=r"(r3) : "r"(p))
#define MMA(C, a0, a1, a2, a3, b0, b1) \
    asm volatile("mma.sync.aligned.m16n8k16.row.col.f32.f16.f16.f32 " \
        "{%0,%1,%2,%3}, {%4,%5,%6,%7}, {%8,%9}, {%0,%1,%2,%3};" \
        : "+f"((C)[0]), "+f"((C)[1]), "+f"((C)[2]), "+f"((C)[3]) \
        : "r"(a0), "r"(a1), "r"(a2), "r"(a3), "r"(b0), "r"(b1))
#define CP16(dst, src) \
    asm volatile("cp.async.cg.shared.global [%0], [%1], 16;" :: "r"(dst), "l"(src))
#define CP_COMMIT() asm volatile("cp.async.commit_group;" ::: "memory")
#define CP_WAIT0() asm volatile("cp.async.wait_group 0;" ::: "memory")

// ---- prepass: convert fp32 W tables to fp16 global; block 0 resets tile queue
__global__ void wcvt_kernel(const float* __restrict__ wi, const float* __restrict__ ws) {
    if (blockIdx.x == 0 && threadIdx.x == 0) g_tile_ctr = 0;
    int i = blockIdx.x * blockDim.x + threadIdx.x;
    __half2* dst = (__half2*)Wh;
    if (i < 32768) {
        float4 v = __ldg((const float4*)wi + i);
        dst[i * 2]     = __floats2half2_rn(v.x, v.y);
        dst[i * 2 + 1] = __floats2half2_rn(v.z, v.w);
    }
    if (i < 65536) {
        float4 v = __ldg((const float4*)ws + i);
        __half2* d2 = (__half2*)(Wh + 512 * 256);
        d2[i * 2]     = __floats2half2_rn(v.x, v.y);
        d2[i * 2 + 1] = __floats2half2_rn(v.z, v.w);
    }
}

__global__ void __launch_bounds__(THREADS, 2)
label_attn_fp16(const float* __restrict__ x_intent,
                const float* __restrict__ x_slot,
                float* __restrict__ out)
{
    extern __shared__ char smem[];
    const uint32_t sb = smem_u32(smem);
    const int tid = threadIdx.x, lane = tid & 31, warp = tid >> 5;
    const int wm = warp >> 1, wh = warp & 1;   // GEMM1 roles
    const int nw = warp;                       // GEMM2 role: n32 column slice

    // ---- per-thread addressing (tile-invariant)
    const int lo7 = lane & 7, hi = lane >> 4, g8 = ((lane >> 3) & 1) << 3;
    const int gg = lane >> 2, tt = lane & 3;
    const uint32_t xa_row = sb + XS + (wm * 16 + lo7 + g8) * 512;
    const int xa_sw = (wm * 16 + lo7 + g8) & 7;
    const uint32_t wb_row = (wh * 16 + lo7 + g8) * 512;      // GEMM1 B rows = labels
    const uint32_t pa_base = sb + PS + (lo7 + g8) * 144;     // GEMM2 A rows
    const uint32_t b2_row = (lo7 + g8) * 512;                // GEMM2 B rows = labels (k)
    const uint32_t ps_st = sb + PS + (wm * 16 + gg) * 144 + (wh * 16 + 2 * tt) * 2;
    float* dsm = (float*)(smem + DEN);
    volatile unsigned* tsh = (volatile unsigned*)(smem + TSH);

    // ---- W chunk cp.async loader (explicit table + buffer); one commit per call
    auto issue_w = [&](const __half* Wgp, int chunk, int b) {
        const __half* src0 = Wgp + (size_t)chunk * 32 * 256;
        for (int i = tid; i < 1024; i += THREADS) {
            int r = i >> 5, c = i & 31;
            uint32_t dst = sb + WS + b * 16384 + r * 512 + ((c ^ (r & 7)) << 4);
            CP16(dst, src0 + r * 256 + c * 8);
        }
        CP_COMMIT();
    };

    // ---- prologue dequeue (first tile only)
    if (tid == 0) *tsh = atomicAdd(&g_tile_ctr, 1u);
    __syncthreads();
    unsigned t = *tsh;
    bool pref = false;   // true when W(0),W(1) of tile t already in flight + X L2-warm

    while (t < N_TILES) {
        const int branch = (t < 512) ? 1 : 0;  // slot tiles first (longest jobs)
        const int tile = branch ? (int)t : (int)t - 512;
        const float* __restrict__ Xin = branch ? x_slot : x_intent;
        const __half* __restrict__ Wg = Wh + (branch ? 512 * 256 : 0);
        float* __restrict__ Oout = out + (size_t)branch * ROWS * D_DIM;
        const int nch = branch ? 32 : 16;
        const long row0 = (long)tile * TILE_M;

        if (!pref) { issue_w(Wg, 0, 0); issue_w(Wg, 1, 1); }

        // ---- X tile: fp32 gmem (L2-warm when prefetched) -> fp16 swizzled smem, *log2(e)
        {
            const float L2E = 1.4426950408889634f;
            const float4* X4 = (const float4*)(Xin + row0 * D_DIM);
            for (int i = tid; i < TILE_M * 64; i += THREADS) {
                int r = i >> 6, c4 = i & 63;
                float4 v = __ldg(&X4[r * 64 + c4]);
                uint32_t h0 = pack2(v.x * L2E, v.y * L2E), h1 = pack2(v.z * L2E, v.w * L2E);
                int ck = c4 >> 1;
                uint32_t dst = sb + XS + r * 512 + ((ck ^ (r & 7)) << 4) + ((c4 & 1) << 3);
                asm volatile("st.shared.v2.b32 [%0], {%1, %2};"
                             :: "r"(dst), "r"(h0), "r"(h1) : "memory");
            }
        }

        float Oa[64];
#pragma unroll
        for (int j = 0; j < 64; j++) Oa[j] = 0.0f;
        float den0 = 0.0f, den1 = 0.0f;
        unsigned tn = 0xFFFFFFFFu;

        const int npair = nch >> 1;
        for (int j = 0; j < npair; j++) {
            const int c = 2 * j;
            const uint32_t WLo = sb + WS + ((c & 3) << 14);
            const uint32_t WHi = sb + WS + (((c + 1) & 3) << 14);
            CP_WAIT0();        // W(c), W(c+1) resident
            __syncthreads();   // sync(a): W visible; all threads past G2(j-1)

            if (c + 3 < nch) { issue_w(Wg, c + 2, (c + 2) & 3); issue_w(Wg, c + 3, (c + 3) & 3); }

            // ---- GEMM1 pair: each X A-frag feeds both chunks' MMAs
            float S[16];
#pragma unroll
            for (int k = 0; k < 16; k++) S[k] = 0.0f;
#pragma unroll
            for (int kk = 0; kk < 16; kk++) {
                uint32_t a0, a1, a2, a3, b0, b1, b2, b3;
                LDSM_X4(a0, a1, a2, a3, xa_row + (((2 * kk + hi) ^ xa_sw) << 4));
                LDSM_X4(b0, b1, b2, b3, WLo + wb_row + (((2 * kk + hi) ^ lo7) << 4));
                MMA(S,      a0, a1, a2, a3, b0, b2);
                MMA(S + 4,  a0, a1, a2, a3, b1, b3);
                LDSM_X4(b0, b1, b2, b3, WHi + wb_row + (((2 * kk + hi) ^ lo7) << 4));
                MMA(S + 8,  a0, a1, a2, a3, b0, b2);
                MMA(S + 12, a0, a1, a2, a3, b1, b3);
            }

            // ---- softmax piece: pack logits (fp16x2), ex2 in fp16x2, store P pair
            uint32_t pk[8];
            pk[0] = hex2(pack2(S[0],  S[1]));  pk[1] = hex2(pack2(S[2],  S[3]));
            pk[2] = hex2(pack2(S[4],  S[5]));  pk[3] = hex2(pack2(S[6],  S[7]));
            pk[4] = hex2(pack2(S[8],  S[9]));  pk[5] = hex2(pack2(S[10], S[11]));
            pk[6] = hex2(pack2(S[12], S[13])); pk[7] = hex2(pack2(S[14], S[15]));
            asm volatile("st.shared.b32 [%0], %1;" :: "r"(ps_st),        "r"(pk[0]) : "memory");
            asm volatile("st.shared.b32 [%0], %1;" :: "r"(ps_st + 16),   "r"(pk[2]) : "memory");
            asm volatile("st.shared.b32 [%0], %1;" :: "r"(ps_st + 1152), "r"(pk[1]) : "memory");
            asm volatile("st.shared.b32 [%0], %1;" :: "r"(ps_st + 1168), "r"(pk[3]) : "memory");
            asm volatile("st.shared.b32 [%0], %1;" :: "r"(ps_st + 64),   "r"(pk[4]) : "memory");
            asm volatile("st.shared.b32 [%0], %1;" :: "r"(ps_st + 80),   "r"(pk[6]) : "memory");
            asm volatile("st.shared.b32 [%0], %1;" :: "r"(ps_st + 1216), "r"(pk[5]) : "memory");
            asm volatile("st.shared.b32 [%0], %1;" :: "r"(ps_st + 1232), "r"(pk[7]) : "memory");

            // early dequeue for the next tile (published by sync(b))
            if (j == npair - 1 && tid == 0) *tsh = atomicAdd(&g_tile_ctr, 1u);
            __syncthreads();   // sync(b): P pair visible (+ tn broadcast on last pair)

            // den adds (fp32 from the same fp16-rounded exps stored in P)
            {
                float2 f0 = unpk(pk[0]), f2 = unpk(pk[2]), f4 = unpk(pk[4]), f6 = unpk(pk[6]);
                den0 += (f0.x + f0.y) + (f2.x + f2.y) + (f4.x + f4.y) + (f6.x + f6.y);
                float2 f1 = unpk(pk[1]), f3 = unpk(pk[3]), f5 = unpk(pk[5]), f7 = unpk(pk[7]);
                den1 += (f1.x + f1.y) + (f3.x + f3.y) + (f5.x + f5.y) + (f7.x + f7.y);
            }

            // ---- last pair: kick off next tile's W cp.async (bufs 0,1 are dead:
            //      last read by G2 of pair npair-2, sequenced before this pair's
            //      sync(a)) and warm next tile's X in L2. Overlaps with G2 below.
            if (j == npair - 1) {
                tn = *tsh;
                if (tn < N_TILES) {
                    const int br2 = (tn < 512) ? 1 : 0;
                    const int tile2 = br2 ? (int)tn : (int)tn - 512;
                    const __half* Wg2 = Wh + (br2 ? 512 * 256 : 0);
                    const float* Xin2 = br2 ? x_slot : x_intent;
                    issue_w(Wg2, 0, 0);
                    issue_w(Wg2, 1, 1);
                    const char* xp = (const char*)(Xin2 + (size_t)tile2 * TILE_M * D_DIM);
                    pfl2(xp + tid * 128);            // 512 lines of 128B = 64KB
                    pfl2(xp + (256 + tid) * 128);
                }
            }

            // ---- GEMM2 pair: warp owns cols [nw*32,+32), all 64 rows, k=64
#pragma unroll
            for (int ks = 0; ks < 4; ks++) {
                const uint32_t Wb = (ks < 2) ? WLo : WHi;
                const int ksl = ks & 1;
                uint32_t a[4][4];
#pragma unroll
                for (int mt = 0; mt < 4; mt++)
                    LDSM_X4(a[mt][0], a[mt][1], a[mt][2], a[mt][3],
                            pa_base + mt * 2304 + ks * 32 + hi * 16);
#pragma unroll
                for (int nt = 0; nt < 2; nt++) {
                    uint32_t r0, r1, r2, r3;
                    int nc_ = nw * 4 + 2 * nt + hi;
                    LDSM_X4T(r0, r1, r2, r3,
                             Wb + (ksl << 13) + b2_row + ((nc_ ^ lo7) << 4));
#pragma unroll
                    for (int mt = 0; mt < 4; mt++) {
                        MMA(Oa + (mt * 4 + nt * 2) * 4,     a[mt][0], a[mt][1], a[mt][2], a[mt][3], r0, r1);
                        MMA(Oa + (mt * 4 + nt * 2 + 1) * 4, a[mt][0], a[mt][1], a[mt][2], a[mt][3], r2, r3);
                    }
                }
            }
        }

        // ---- denominators: quad reduce, publish halves; per-thread approx reciprocals
        den0 += __shfl_xor_sync(0xffffffff, den0, 1);
        den0 += __shfl_xor_sync(0xffffffff, den0, 2);
        den1 += __shfl_xor_sync(0xffffffff, den1, 1);
        den1 += __shfl_xor_sync(0xffffffff, den1, 2);
        __syncthreads();       // all G2 done; DEN area free
        if (tt == 0) {
            dsm[wh * 64 + wm * 16 + gg]     = den0;
            dsm[wh * 64 + wm * 16 + gg + 8] = den1;
        }
        __syncthreads();

        // ---- scaled store: warp nw covers rows 0..63, cols nw*32..+31
#pragma unroll
        for (int mt = 0; mt < 4; mt++) {
            const int ra_l = mt * 16 + gg;
            const float ia = rcpf(dsm[ra_l]     + dsm[64 + ra_l]);
            const float ib = rcpf(dsm[ra_l + 8] + dsm[64 + ra_l + 8]);
            const long r_a = row0 + ra_l, r_b = r_a + 8;
#pragma unroll
            for (int t4 = 0; t4 < 4; t4++) {
                int cc = nw * 32 + t4 * 8 + 2 * tt;
                int idx = (mt * 4 + t4) * 4;
                *(float2*)&Oout[r_a * 256 + cc] = make_float2(Oa[idx]     * ia, Oa[idx + 1] * ia);
                *(float2*)&Oout[r_b * 256 + cc] = make_float2(Oa[idx + 2] * ib, Oa[idx + 3] * ib);
            }
        }

        t = tn;
        pref = (tn < N_TILES);
    }
}

extern "C" void kernel_launch(void* const* d_in, const int* in_sizes, int n_in,
                              void* d_out, int out_size)
{
    const float* x_intent = (const float*)d_in[0];
    const float* x_slot   = (const float*)d_in[1];
    // d_in[2] = mask (unused)
    const float* w_intent = (const float*)d_in[3];
    const float* w_slot   = (const float*)d_in[4];
    float* out = (float*)d_out;

    wcvt_kernel<<<256, 256>>>(w_intent, w_slot);   // also resets g_tile_ctr

    cudaFuncSetAttribute(label_attn_fp16,
                         cudaFuncAttributeMaxDynamicSharedMemorySize, SMEM_BYTES);
    label_attn_fp16<<<296, THREADS, SMEM_BYTES>>>(x_intent, x_slot, out);
}